// round 12
// baseline (speedup 1.0000x reference)
#include <cuda_runtime.h>
#include <cstdint>

// AccuracyMetricLoss: per-day (96-elem) RMS relative-error score, mean over days.
// score_d = (1 - sqrt(mean_j ((t-p)/max(t,thresh))^2)) * 100 ; out = mean_d score_d
//
// R12: bulk-async (TMA/UBLKCP) pipeline, de-risked vs R11:
//  - stage = 28 days -> dynamic smem 43008B (safely under the 48KB no-opt-in cap)
//  - NO empty mbarriers: consumer release = __syncthreads(); thread 0 reissues
//    slot b two stages later (no overlap possible). Only full-side mbarrier +
//    cp.async.bulk remain (the test_tma.cu-validated pattern).
//  - fence.proxy.async before reissue (generic reads -> async writes ordering).
//  - 592 CTAs x 256 thr, contiguous per-CTA day ranges; warps 0-6 compute 4
//    days each per stage (warp 7 idle; memory-bound, compute has 3x headroom).
//  - last-block-finalizes (deterministic fixed-order double sum, counter reset).

#define T_LEN 96
#define F4_PER_DAY 24
#define DAY_BYTES 384
#define STAGE_DAYS 28
#define STAGE_ARR_BYTES (STAGE_DAYS * DAY_BYTES)   // 10752
#define STAGE_BYTES (2 * STAGE_ARR_BYTES)          // 21504 (tru + pred)
#define SMEM_DYN (2 * STAGE_BYTES)                 // 43008

#define NBLOCKS 592          // 4 * 148 SMs
#define NTHREADS 256         // 8 warps

__device__ float g_partials[NBLOCKS];
__device__ unsigned int g_counter = 0;

__device__ __forceinline__ uint32_t smem_u32(const void* p)
{
    uint32_t a;
    asm("{ .reg .u64 t; cvta.to.shared.u64 t, %1; cvt.u32.u64 %0, t; }"
        : "=r"(a) : "l"(p));
    return a;
}
__device__ __forceinline__ void mbar_init(uint32_t mbar, uint32_t count)
{
    asm volatile("mbarrier.init.shared.b64 [%0], %1;" :: "r"(mbar), "r"(count) : "memory");
}
__device__ __forceinline__ void mbar_expect_tx(uint32_t mbar, uint32_t bytes)
{
    asm volatile("mbarrier.arrive.expect_tx.shared.b64 _, [%0], %1;"
                 :: "r"(mbar), "r"(bytes) : "memory");
}
__device__ __forceinline__ void mbar_wait(uint32_t mbar, uint32_t parity)
{
    uint32_t done;
    asm volatile(
        "{\n\t.reg .pred p;\n\t"
        "mbarrier.try_wait.parity.acquire.cta.shared::cta.b64 p, [%1], %2;\n\t"
        "selp.b32 %0, 1, 0, p;\n\t}"
        : "=r"(done) : "r"(mbar), "r"(parity) : "memory");
    if (!done) {
        asm volatile(
            "{\n\t.reg .pred P1;\n\t"
            "W_%=:\n\t"
            "mbarrier.try_wait.parity.acquire.cta.shared::cta.b64 P1, [%0], %1, 0x989680;\n\t"
            "@P1 bra.uni D_%=;\n\t"
            "bra.uni W_%=;\n\t"
            "D_%=:\n\t}"
            :: "r"(mbar), "r"(parity) : "memory");
    }
}
__device__ __forceinline__ void bulk_g2s(uint32_t dst_smem, const void* src, uint32_t bytes,
                                         uint32_t mbar)
{
    asm volatile(
        "cp.async.bulk.shared::cluster.global.mbarrier::complete_tx::bytes [%0], [%1], %2, [%3];"
        :: "r"(dst_smem), "l"(src), "r"(bytes), "r"(mbar) : "memory");
}
__device__ __forceinline__ void fence_proxy_async_cta()
{
    asm volatile("fence.proxy.async.shared::cta;" ::: "memory");
}

__device__ __forceinline__ float day_err_sq(float4 t, float4 p, float thresh)
{
    float d0 = (t.x > thresh) ? t.x : thresh;
    float d1 = (t.y > thresh) ? t.y : thresh;
    float d2 = (t.z > thresh) ? t.z : thresh;
    float d3 = (t.w > thresh) ? t.w : thresh;
    float e0 = __fdividef(t.x - p.x, d0);
    float e1 = __fdividef(t.y - p.y, d1);
    float e2 = __fdividef(t.z - p.z, d2);
    float e3 = __fdividef(t.w - p.w, d3);
    return e0 * e0 + e1 * e1 + e2 * e2 + e3 * e3;
}

__global__ __launch_bounds__(NTHREADS, 4) void score_kernel(
    const float* __restrict__ pred,
    const float* __restrict__ tru,
    float* __restrict__ out,
    int num_days)
{
    extern __shared__ __align__(16) char dyn_smem[];
    __shared__ __align__(8) unsigned long long mb_full[2];

    const float cap    = 1602.1333333333334f;
    const float thresh = 0.2f * cap;
    const float inv_T  = 1.0f / 96.0f;

    const int tid  = threadIdx.x;
    const int lane = tid & 31;
    const int wid  = tid >> 5;
    const int g    = lane >> 3;          // day group within warp-trip (0..3)
    const int k    = lane & 7;

    const int day_s = (int)(((long)blockIdx.x       * num_days) / NBLOCKS);
    const int day_e = (int)(((long)(blockIdx.x + 1) * num_days) / NBLOCKS);
    const int nstages = (day_e - day_s + STAGE_DAYS - 1) / STAGE_DAYS;

    const uint32_t full0 = smem_u32(&mb_full[0]);
    const uint32_t full1 = smem_u32(&mb_full[1]);
    const uint32_t smem_base = smem_u32(dyn_smem);

    if (tid == 0) {
        mbar_init(full0, 1);
        mbar_init(full1, 1);
    }
    __syncthreads();

    auto issue = [&](int s) {
        const int b = s & 1;
        const long gday = (long)day_s + (long)s * STAGE_DAYS;
        const int nd_s = min(STAGE_DAYS, day_e - (int)gday);
        const uint32_t bytes = (uint32_t)nd_s * DAY_BYTES;
        const uint32_t mbar = b ? full1 : full0;
        const uint32_t dst  = smem_base + (uint32_t)b * STAGE_BYTES;
        mbar_expect_tx(mbar, 2u * bytes);
        bulk_g2s(dst,                   tru  + gday * T_LEN, bytes, mbar);
        bulk_g2s(dst + STAGE_ARR_BYTES, pred + gday * T_LEN, bytes, mbar);
    };

    if (tid == 0) {
        issue(0);
        if (nstages > 1) issue(1);
    }

    uint32_t cph0 = 0, cph1 = 0;
    float acc = 0.0f;

    for (int s = 0; s < nstages; s++) {
        const int b = s & 1;
        if (b == 0) { mbar_wait(full0, cph0); cph0 ^= 1; }
        else        { mbar_wait(full1, cph1); cph1 ^= 1; }

        const int nd_s = min(STAGE_DAYS, day_e - (day_s + s * STAGE_DAYS));
        const int wd   = wid * 4;
        const int ndw  = min(4, nd_s - wd);

        const float4* tb = (const float4*)(dyn_smem + (size_t)b * STAGE_BYTES);
        const float4* pb = (const float4*)(dyn_smem + (size_t)b * STAGE_BYTES + STAGE_ARR_BYTES);

        if (ndw == 4) {
            const int idx = (wd + g) * F4_PER_DAY + k;
            float4 t0 = tb[idx];
            float4 t1 = tb[idx + 8];
            float4 t2 = tb[idx + 16];
            float4 p0 = pb[idx];
            float4 p1 = pb[idx + 8];
            float4 p2 = pb[idx + 16];

            float r = day_err_sq(t0, p0, thresh)
                    + day_err_sq(t1, p1, thresh)
                    + day_err_sq(t2, p2, thresh);

            r += __shfl_xor_sync(0xffffffffu, r, 4);
            r += __shfl_xor_sync(0xffffffffu, r, 2);
            r += __shfl_xor_sync(0xffffffffu, r, 1);

            acc += (1.0f - sqrtf(r * inv_T)) * 100.0f;   // counted 8x per day
        } else if (ndw > 0) {
            float r = 0.0f;
            if (g < ndw) {
                const int idx = (wd + g) * F4_PER_DAY + k;
                float4 t0 = tb[idx];
                float4 t1 = tb[idx + 8];
                float4 t2 = tb[idx + 16];
                float4 p0 = pb[idx];
                float4 p1 = pb[idx + 8];
                float4 p2 = pb[idx + 16];
                r = day_err_sq(t0, p0, thresh)
                  + day_err_sq(t1, p1, thresh)
                  + day_err_sq(t2, p2, thresh);
            }
            r += __shfl_xor_sync(0xffffffffu, r, 4);
            r += __shfl_xor_sync(0xffffffffu, r, 2);
            r += __shfl_xor_sync(0xffffffffu, r, 1);
            if (g < ndw)
                acc += (1.0f - sqrtf(r * inv_T)) * 100.0f;
        }

        __syncthreads();   // all consumers done with slot b

        if (tid == 0 && s + 2 < nstages) {
            fence_proxy_async_cta();   // order generic reads before async writes
            issue(s + 2);              // safe: slot b not read until stage s+2 wait
        }
    }

    // warp sum, then block reduce into g_partials[blockIdx.x]
    #pragma unroll
    for (int o = 16; o > 0; o >>= 1)
        acc += __shfl_xor_sync(0xffffffffu, acc, o);

    __shared__ float warp_acc[NTHREADS / 32];
    if (lane == 0) warp_acc[wid] = acc;
    __syncthreads();

    __shared__ bool is_last;
    if (tid == 0) {
        float v = 0.0f;
        #pragma unroll
        for (int w = 0; w < NTHREADS / 32; w++) v += warp_acc[w];
        g_partials[blockIdx.x] = v;
        __threadfence();
        unsigned int prev = atomicAdd(&g_counter, 1u);
        is_last = (prev == (unsigned int)(gridDim.x - 1));
    }
    __syncthreads();

    if (is_last && tid < 32) {
        double a = 0.0;
        for (int i = tid; i < NBLOCKS; i += 32)
            a += (double)__ldg(&g_partials[i]);
        #pragma unroll
        for (int o = 16; o > 0; o >>= 1)
            a += __shfl_xor_sync(0xffffffffu, a, o);
        if (tid == 0) {
            out[0] = (float)(a / (8.0 * (double)num_days));
            g_counter = 0;           // reset for next graph replay
            __threadfence();
        }
    }
}

extern "C" void kernel_launch(void* const* d_in, const int* in_sizes, int n_in,
                              void* d_out, int out_size)
{
    const float* pred = (const float*)d_in[0];
    const float* tru  = (const float*)d_in[1];
    float* out = (float*)d_out;

    int num_days = in_sizes[0] / T_LEN;

    score_kernel<<<NBLOCKS, NTHREADS, SMEM_DYN>>>(pred, tru, out, num_days);
}

// round 13
// speedup vs baseline: 1.2357x; 1.2357x over previous
#include <cuda_runtime.h>

// AccuracyMetricLoss: per-day (96-elem) RMS relative-error score, mean over days.
// score_d = (1 - sqrt(mean_j ((t-p)/max(t,thresh))^2)) * 100 ; out = mean_d score_d
//
// FINAL (converged): best measured configuration, reproduced twice at 31.2us
// (ncu kernel 30.1-31.0us, ~5.1TB/s). The R4-R12 experiment matrix — occupancy
// 37/50/62/93%, scalar vs float4 vs sw-pipelined LDG, ldcs vs default policy,
// and a cp.async.bulk (TMA) smem pipeline — all land in 4.7-5.2TB/s; the
// ceiling is a platform memory-system property (path-independent per
// B300_MICROARCH), not a kernel-structure one. This kernel sits at that
// ceiling with single-launch overhead already fused away.
//
//  - 8-lanes-per-day float4 layout: 6 batched, fully-coalesced LDG.128/trip.
//  - __ldcs evict-first streaming loads (dataset 153.6MB >> 126MB L2).
//  - __launch_bounds__(256,4), 592 blocks, contiguous per-warp day ranges
//    (near-perfect balance, <=1 day skew).
//  - 3-shuffle in-group day reduction; score counted 8x/day, divided at end.
//  - last-block-finalizes: fixed-order double reduction (deterministic),
//    counter self-resets => graph-replayable.

#define T_LEN 96
#define F4_PER_DAY 24
#define NBLOCKS 592          // 4 * 148 SMs
#define NTHREADS 256         // 8 warps/block
#define WARPS_PER_BLOCK (NTHREADS / 32)
#define TOTAL_WARPS (NBLOCKS * WARPS_PER_BLOCK)

__device__ float g_partials[NBLOCKS];
__device__ unsigned int g_counter = 0;

__device__ __forceinline__ float day_err_sq(float4 t, float4 p, float thresh)
{
    float d0 = (t.x > thresh) ? t.x : thresh;
    float d1 = (t.y > thresh) ? t.y : thresh;
    float d2 = (t.z > thresh) ? t.z : thresh;
    float d3 = (t.w > thresh) ? t.w : thresh;
    float e0 = __fdividef(t.x - p.x, d0);
    float e1 = __fdividef(t.y - p.y, d1);
    float e2 = __fdividef(t.z - p.z, d2);
    float e3 = __fdividef(t.w - p.w, d3);
    return e0 * e0 + e1 * e1 + e2 * e2 + e3 * e3;
}

__global__ __launch_bounds__(NTHREADS, 4) void score_kernel(
    const float* __restrict__ pred,
    const float* __restrict__ tru,
    float* __restrict__ out,
    int num_days)
{
    const float cap    = 1602.1333333333334f;
    const float thresh = 0.2f * cap;
    const float inv_T  = 1.0f / 96.0f;

    const int lane = threadIdx.x & 31;
    const int g    = lane >> 3;          // day group within warp (0..3)
    const int k    = lane & 7;           // lane within group
    const int warp = (blockIdx.x * WARPS_PER_BLOCK) + (threadIdx.x >> 5);

    const float4* __restrict__ tru4  = (const float4*)tru;
    const float4* __restrict__ pred4 = (const float4*)pred;

    // contiguous per-warp day range: near-perfect balance (<=1 day skew)
    int day_s = (int)(((long)warp       * num_days) / TOTAL_WARPS);
    int day_e = (int)(((long)(warp + 1) * num_days) / TOTAL_WARPS);

    float acc = 0.0f;

    int day = day_s;
    for (; day + 4 <= day_e; day += 4) {
        // 6 fully-coalesced LDG.128 per warp, batched
        const long b = (long)(day + g) * F4_PER_DAY + k;
        float4 t0 = __ldcs(tru4  + b);
        float4 t1 = __ldcs(tru4  + b + 8);
        float4 t2 = __ldcs(tru4  + b + 16);
        float4 p0 = __ldcs(pred4 + b);
        float4 p1 = __ldcs(pred4 + b + 8);
        float4 p2 = __ldcs(pred4 + b + 16);

        float r = day_err_sq(t0, p0, thresh)
                + day_err_sq(t1, p1, thresh)
                + day_err_sq(t2, p2, thresh);

        // reduce within 8-lane group (xor of low 3 bits stays in-group)
        r += __shfl_xor_sync(0xffffffffu, r, 4);
        r += __shfl_xor_sync(0xffffffffu, r, 2);
        r += __shfl_xor_sync(0xffffffffu, r, 1);

        acc += (1.0f - sqrtf(r * inv_T)) * 100.0f;   // counted 8x per day
    }

    // tail: 0..3 days, groups g < nd active, same float4 path
    {
        const int nd = day_e - day;
        if (nd > 0) {
            float r = 0.0f;
            if (g < nd) {
                const long b = (long)(day + g) * F4_PER_DAY + k;
                float4 t0 = __ldcs(tru4  + b);
                float4 t1 = __ldcs(tru4  + b + 8);
                float4 t2 = __ldcs(tru4  + b + 16);
                float4 p0 = __ldcs(pred4 + b);
                float4 p1 = __ldcs(pred4 + b + 8);
                float4 p2 = __ldcs(pred4 + b + 16);
                r = day_err_sq(t0, p0, thresh)
                  + day_err_sq(t1, p1, thresh)
                  + day_err_sq(t2, p2, thresh);
            }
            r += __shfl_xor_sync(0xffffffffu, r, 4);
            r += __shfl_xor_sync(0xffffffffu, r, 2);
            r += __shfl_xor_sync(0xffffffffu, r, 1);
            if (g < nd)
                acc += (1.0f - sqrtf(r * inv_T)) * 100.0f;
        }
    }

    // warp sum, then block reduce into g_partials[blockIdx.x]
    #pragma unroll
    for (int o = 16; o > 0; o >>= 1)
        acc += __shfl_xor_sync(0xffffffffu, acc, o);

    __shared__ float warp_acc[WARPS_PER_BLOCK];
    if (lane == 0) warp_acc[threadIdx.x >> 5] = acc;
    __syncthreads();

    __shared__ bool is_last;
    if (threadIdx.x == 0) {
        float v = 0.0f;
        #pragma unroll
        for (int w = 0; w < WARPS_PER_BLOCK; w++) v += warp_acc[w];
        g_partials[blockIdx.x] = v;
        __threadfence();
        unsigned int prev = atomicAdd(&g_counter, 1u);
        is_last = (prev == (unsigned int)(gridDim.x - 1));
    }
    __syncthreads();

    // last block finalizes: fixed-order double reduction over NBLOCKS partials
    if (is_last) {
        double a = 0.0;
        for (int i = threadIdx.x; i < NBLOCKS; i += NTHREADS)
            a += (double)g_partials[i];

        __shared__ double dacc[WARPS_PER_BLOCK];
        #pragma unroll
        for (int o = 16; o > 0; o >>= 1)
            a += __shfl_xor_sync(0xffffffffu, a, o);
        if (lane == 0) dacc[threadIdx.x >> 5] = a;
        __syncthreads();
        if (threadIdx.x == 0) {
            double s = 0.0;
            #pragma unroll
            for (int w = 0; w < WARPS_PER_BLOCK; w++) s += dacc[w];
            out[0] = (float)(s / (8.0 * (double)num_days));
            g_counter = 0;           // reset for next graph replay
            __threadfence();
        }
    }
}

extern "C" void kernel_launch(void* const* d_in, const int* in_sizes, int n_in,
                              void* d_out, int out_size)
{
    const float* pred = (const float*)d_in[0];
    const float* tru  = (const float*)d_in[1];
    float* out = (float*)d_out;

    int num_days = in_sizes[0] / T_LEN;

    score_kernel<<<NBLOCKS, NTHREADS>>>(pred, tru, out, num_days);
}